// round 16
// baseline (speedup 1.0000x reference)
#include <cuda_runtime.h>
#include <cuda_fp16.h>
#include <math.h>

// Problem constants (fixed dataset: N=50000, E=1.6M, avg in-degree 32)
#define MAXN 50048
#define CAP  128           // per-node adjacency capacity; Poisson(32) max << 128
#define ZROW (MAXN - 1)    // guaranteed all-zero row (never written; BSS zero-init)

struct Consts {
    float Mz[4][32];    // 0.5 * Wz @ Lz[0:32,:]   (0.5 from tanh(pz/2) folded in)
    float Mh[4][32];    // Wh @ Lh[0:32,:]
    float cz[32];       // 0.5 * (bz @ Lz[0:32,:] + lz)
    float ch[32];       // bh @ Lh[0:32,:] + lh
    float probs[12];    // 0.5 * softmax(attention)  (0.5 from GRU identity)
    float2 Wo2[16][32]; // Wo2[p][lane] = (Wo[2p][lane], Wo[2p+1][lane]); 0 for lane>=12
    float bo[12];
};
#define CONSTS_FLOATS (sizeof(Consts) / 4)

__device__ Consts g_c;
__device__ int   g_cnt[MAXN];               // zero-init at load; k_cvt re-zeroes
__device__ int   g_deg[MAXN];
__device__ float g_dinv[MAXN];
__device__ int   g_adj[(size_t)MAXN * CAP];
// One node row = 128 B = 8 x uint4: chunks 0-5 = 48 fp16 values of
// x[node]*dinv[node] in ORIGINAL order (flat idx f*12+t), chunks 6-7 zero.
// 128B-aligned rows: each gathered row = ONE L1 line. Rows >= n stay zero.
__device__ __align__(128) uint4 g_xh[(size_t)MAXN * 8];

// Packed f32x2 helpers (sm_103a packed-FMA pipe)
#define PACK2(out, lo, hi) \
    asm("mov.b64 %0, {%1, %2};" : "=l"(out) : "r"(__float_as_uint(lo)), "r"(__float_as_uint(hi)))
#define UNPACK2(lo, hi, in) \
    do { unsigned _a, _b; \
         asm("mov.b64 {%0, %1}, %2;" : "=r"(_a), "=r"(_b) : "l"(in)); \
         lo = __uint_as_float(_a); hi = __uint_as_float(_b); } while (0)
#define FMA2(d, a, b, c) \
    asm("fma.rn.f32x2 %0, %1, %2, %3;" : "=l"(d) : "l"(a), "l"(b), "l"(c))

// ---------------------------------------------------------------------------
// Kernel 1: bucketed adjacency build — best known config (R7): 256-thread
// blocks, 4 edges/thread.
// ---------------------------------------------------------------------------
__global__ void k_fill(const int* __restrict__ ei, int e) {
    int t = blockIdx.x * blockDim.x + threadIdx.x;
    int i4 = t * 4;
    if (i4 >= e) return;
    if ((e & 3) == 0) {   // dataset path: e divisible by 4
        int4 r = *reinterpret_cast<const int4*>(ei + i4);       // sources
        int4 c = *reinterpret_cast<const int4*>(ei + e + i4);   // targets
        int p0 = atomicAdd(&g_cnt[c.x], 1);
        int p1 = atomicAdd(&g_cnt[c.y], 1);
        int p2 = atomicAdd(&g_cnt[c.z], 1);
        int p3 = atomicAdd(&g_cnt[c.w], 1);
        if (p0 < CAP) g_adj[(size_t)c.x * CAP + p0] = r.x;
        if (p1 < CAP) g_adj[(size_t)c.y * CAP + p1] = r.y;
        if (p2 < CAP) g_adj[(size_t)c.z * CAP + p2] = r.z;
        if (p3 < CAP) g_adj[(size_t)c.w * CAP + p3] = r.w;
    } else {
        int end = min(i4 + 4, e);
        for (int i = i4; i < end; i++) {
            int rr = ei[i], cc = ei[e + i];
            int p = atomicAdd(&g_cnt[cc], 1);
            if (p < CAP) g_adj[(size_t)cc * CAP + p] = rr;
        }
    }
}

// ---------------------------------------------------------------------------
// Kernel 2 (after k_fill): per-node pack + integrated weight fold (block 0).
// dinv = rsqrt(cnt+1); pack fp16(x*dinv) row; write deg/dinv; re-zero cnt.
// ---------------------------------------------------------------------------
__global__ void k_cvt(const float* __restrict__ x, int nchunks,
                      const float* __restrict__ att,
                      const float* __restrict__ Wz, const float* __restrict__ bz,
                      const float* __restrict__ Lz, const float* __restrict__ lz,
                      const float* __restrict__ Wh, const float* __restrict__ bh,
                      const float* __restrict__ Lh, const float* __restrict__ lh,
                      const float* __restrict__ Wo, const float* __restrict__ bo) {
    if (blockIdx.x == 0 && threadIdx.x < 128) {
        int tid = threadIdx.x;
        int f = tid >> 5, c = tid & 31;
        float mz = 0.f, mh = 0.f;
        #pragma unroll 8
        for (int k = 0; k < 32; k++) {
            mz = fmaf(Wz[f * 32 + k], Lz[k * 32 + c], mz);
            mh = fmaf(Wh[f * 32 + k], Lh[k * 32 + c], mh);
        }
        g_c.Mz[f][c] = 0.5f * mz;   // tanh(pz/2): 0.5 folded into the matrix
        g_c.Mh[f][c] = mh;
        if (f == 0) {
            float s1 = lz[c], s2 = lh[c];
            #pragma unroll 8
            for (int k = 0; k < 32; k++) {
                s1 = fmaf(bz[k], Lz[k * 32 + c], s1);
                s2 = fmaf(bh[k], Lh[k * 32 + c], s2);
            }
            g_c.cz[c] = 0.5f * s1;
            g_c.ch[c] = s2;
        }
        // Wo2[p][lane] = (Wo[2p][lane], Wo[2p+1][lane]); lanes >= 12 -> 0
        for (int i = tid; i < 16 * 32; i += 128) {
            int p = i >> 5, cc = i & 31;
            float a = (cc < 12) ? Wo[(2 * p) * 12 + cc] : 0.f;
            float b = (cc < 12) ? Wo[(2 * p + 1) * 12 + cc] : 0.f;
            g_c.Wo2[p][cc] = make_float2(a, b);
        }
        if (tid < 12) g_c.bo[tid] = bo[tid];
        if (tid == 0) {
            float m = -1e30f;
            for (int t = 0; t < 12; t++) m = fmaxf(m, att[t]);
            float ex[12]; float s = 0.f;
            for (int t = 0; t < 12; t++) { ex[t] = expf(att[t] - m); s += ex[t]; }
            float inv = 0.5f / s;   // 0.5 from (1-sigmoid)*tanh identity
            for (int t = 0; t < 12; t++) g_c.probs[t] = ex[t] * inv;
        }
    }

    int i = blockIdx.x * blockDim.x + threadIdx.x;   // one uint4 out
    int node = i >> 3, h = i & 7;
    int d = 0;
    if (i < nchunks) d = g_cnt[node];
    __syncwarp();
    if (i >= nchunks) return;
    float dv = rsqrtf((float)d + 1.0f);   // +1 self loop
    uint4 o = make_uint4(0u, 0u, 0u, 0u);
    if (h < 6) {
        const float4* src = (const float4*)(x + (size_t)node * 48 + h * 8);
        float4 a = src[0];
        float4 b = src[1];
        __half2 h0 = __floats2half2_rn(a.x * dv, a.y * dv);
        __half2 h1 = __floats2half2_rn(a.z * dv, a.w * dv);
        __half2 h2 = __floats2half2_rn(b.x * dv, b.y * dv);
        __half2 h3 = __floats2half2_rn(b.z * dv, b.w * dv);
        o.x = *reinterpret_cast<unsigned*>(&h0);
        o.y = *reinterpret_cast<unsigned*>(&h1);
        o.z = *reinterpret_cast<unsigned*>(&h2);
        o.w = *reinterpret_cast<unsigned*>(&h3);
    } else if (h == 7) {
        g_cnt[node] = 0;                       // ready for next replay
        g_deg[node] = (d < CAP) ? d : CAP;
        g_dinv[node] = dv;
    }
    g_xh[i] = o;
}

// ---------------------------------------------------------------------------
// Kernel 3: fused warp-per-node gather + GRU.
// Mainloop: 32-edge groups — all 32 lanes prefetch adj, 8 back-to-back inner
// LDG.128 steps (MLP 8, was 4); fp16 accumulation depth <= 9, ONE flush per
// group. Epilogue: f32x2 GRU (tanh(pz/2) fold) + f32x2 output projection.
// ---------------------------------------------------------------------------
__device__ __forceinline__ float fast_tanh(float v) {
    float r;
    asm("tanh.approx.f32 %0, %1;" : "=f"(r) : "f"(v));
    return r;
}

__device__ __forceinline__ void hadd4(__half2* hacc, const uint4& c) {
    hacc[0] = __hadd2(hacc[0], *reinterpret_cast<const __half2*>(&c.x));
    hacc[1] = __hadd2(hacc[1], *reinterpret_cast<const __half2*>(&c.y));
    hacc[2] = __hadd2(hacc[2], *reinterpret_cast<const __half2*>(&c.z));
    hacc[3] = __hadd2(hacc[3], *reinterpret_cast<const __half2*>(&c.w));
}

__device__ __forceinline__ void flush8(float* acc, __half2* hacc) {
    #pragma unroll
    for (int j = 0; j < 4; j++) {
        float2 f = __half22float2(hacc[j]);
        acc[2 * j]     += f.x;
        acc[2 * j + 1] += f.y;
        hacc[j] = __half2(__ushort_as_half(0), __ushort_as_half(0));
    }
}

__global__ void __launch_bounds__(256, 6) k_fused(float* __restrict__ out, int n) {
    __shared__ __align__(16) float sC[CONSTS_FLOATS];
    __shared__ __align__(16) float sXA[8][48];     // per-warp XA (f-major) / H
    {
        const float* src = (const float*)&g_c;
        for (int i = threadIdx.x; i < (int)CONSTS_FLOATS; i += 256) sC[i] = src[i];
    }
    __syncthreads();
    const Consts* C = (const Consts*)sC;

    const unsigned FULL = 0xffffffffu;
    int warp = threadIdx.x >> 5, lane = threadIdx.x & 31;
    int node = blockIdx.x * 8 + warp;
    if (node >= n) return;

    int myslot = lane >> 3;   // 0..3: which of the 4 concurrent edges
    int h = lane & 7;         // 16B chunk within the row
    int deg = g_deg[node];
    float dn = g_dinv[node];
    const int* adj = g_adj + (size_t)node * CAP;

    float acc[8];
    #pragma unroll
    for (int k = 0; k < 8; k++) acc[k] = 0.f;
    __half2 hacc[4];
    #pragma unroll
    for (int j = 0; j < 4; j++) hacc[j] = __half2(__ushort_as_half(0), __ushort_as_half(0));

    // self loop: own pre-scaled row; final *dn makes it dn^2 * x.
    if (myslot == 0) hadd4(hacc, g_xh[(size_t)node * 8 + h]);

    int iters = (deg + 31) >> 5;   // 32 edges per group, 8 inner steps of 4
    // prefetch group 0's indices (all 32 lanes); pads -> zero row
    int s = (lane < deg) ? adj[lane] : ZROW;

    for (int it = 0; it < iters; it++) {
        int cur_s = s;
        int idx = (it + 1) * 32 + lane;
        s = (idx < deg) ? adj[idx] : ZROW;
        #pragma unroll
        for (int k = 0; k < 8; k++) {
            int row = __shfl_sync(FULL, cur_s, 4 * k + myslot);
            hadd4(hacc, g_xh[(size_t)row * 8 + h]);
        }
        flush8(acc, hacc);   // fp16 depth per group stays <= 9
    }

    // butterfly over the 4 slots (lanes with equal h), then norm.
    #pragma unroll
    for (int d = 8; d < 32; d <<= 1) {
        #pragma unroll
        for (int k = 0; k < 8; k++)
            acc[k] += __shfl_xor_sync(FULL, acc[k], d);
    }
    #pragma unroll
    for (int k = 0; k < 8; k++) acc[k] *= dn;

    // XA to smem in ORIGINAL f-major order (flat idx f*12+t): lane h owns
    // elements 8h..8h+7 -> two contiguous STS.128, no transpose needed.
    float* xaf = sXA[warp];
    if (lane < 6) {
        float4* dst = (float4*)(xaf + lane * 8);
        dst[0] = make_float4(acc[0], acc[1], acc[2], acc[3]);
        dst[1] = make_float4(acc[4], acc[5], acc[6], acc[7]);
    }
    __syncwarp();

    // collapsed GRU: lane = output channel c; t in PAIRS with packed f32x2.
    unsigned long long Mz0p, Mz1p, Mz2p, Mz3p, Mh0p, Mh1p, Mh2p, Mh3p, czp, chp;
    PACK2(Mz0p, C->Mz[0][lane], C->Mz[0][lane]);
    PACK2(Mz1p, C->Mz[1][lane], C->Mz[1][lane]);
    PACK2(Mz2p, C->Mz[2][lane], C->Mz[2][lane]);
    PACK2(Mz3p, C->Mz[3][lane], C->Mz[3][lane]);
    PACK2(Mh0p, C->Mh[0][lane], C->Mh[0][lane]);
    PACK2(Mh1p, C->Mh[1][lane], C->Mh[1][lane]);
    PACK2(Mh2p, C->Mh[2][lane], C->Mh[2][lane]);
    PACK2(Mh3p, C->Mh[3][lane], C->Mh[3][lane]);
    PACK2(czp, C->cz[lane], C->cz[lane]);
    PACK2(chp, C->ch[lane], C->ch[lane]);

    float H = 0.f;
    #pragma unroll
    for (int tp = 0; tp < 6; tp++) {
        unsigned long long xv0 = *(const unsigned long long*)(xaf +      2 * tp);
        unsigned long long xv1 = *(const unsigned long long*)(xaf + 12 + 2 * tp);
        unsigned long long xv2 = *(const unsigned long long*)(xaf + 24 + 2 * tp);
        unsigned long long xv3 = *(const unsigned long long*)(xaf + 36 + 2 * tp);
        unsigned long long pzp, php;
        FMA2(pzp, xv3, Mz3p, czp);
        FMA2(pzp, xv2, Mz2p, pzp);
        FMA2(pzp, xv1, Mz1p, pzp);
        FMA2(pzp, xv0, Mz0p, pzp);
        FMA2(php, xv3, Mh3p, chp);
        FMA2(php, xv2, Mh2p, php);
        FMA2(php, xv1, Mh1p, php);
        FMA2(php, xv0, Mh0p, php);
        float pz0, pz1, ph0, ph1;
        UNPACK2(pz0, pz1, pzp);
        UNPACK2(ph0, ph1, php);
        // (1 - sigmoid(pz)) * tanh(ph) = 0.5*(1 - tanh(pz/2))*tanh(ph);
        // pz/2 folded into Mz/cz, 0.5 into probs.
        float tA0 = fast_tanh(pz0), tB0 = fast_tanh(ph0);
        float tA1 = fast_tanh(pz1), tB1 = fast_tanh(ph1);
        H = fmaf((1.0f - tA0) * tB0, C->probs[2 * tp],     H);
        H = fmaf((1.0f - tA1) * tB1, C->probs[2 * tp + 1], H);
    }

    // Output projection (packed f32x2): reuse smem buffer for relu(H).
    __syncwarp();
    xaf[lane] = fmaxf(H, 0.f);
    __syncwarp();
    if (lane < 12) {
        unsigned long long accp;
        PACK2(accp, C->bo[lane], 0.f);
        #pragma unroll
        for (int p = 0; p < 16; p++) {
            unsigned long long hp = *(const unsigned long long*)(xaf + 2 * p);  // uniform
            unsigned long long wp = *(const unsigned long long*)(&C->Wo2[p][lane]);
            FMA2(accp, hp, wp, accp);
        }
        float lo, hi;
        UNPACK2(lo, hi, accp);
        out[(size_t)node * 12 + lane] = lo + hi;
    }
}

// ---------------------------------------------------------------------------
extern "C" void kernel_launch(void* const* d_in, const int* in_sizes, int n_in,
                              void* d_out, int out_size) {
    const float* x   = (const float*)d_in[0];
    const int*   ei  = (const int*)  d_in[1];
    const float* att = (const float*)d_in[2];
    const float* Wz  = (const float*)d_in[3];
    const float* bz  = (const float*)d_in[4];
    const float* Lz  = (const float*)d_in[5];
    const float* lz  = (const float*)d_in[6];
    // d_in[7..10] = Wr, br, Lr, lr : provably unused (H0 == 0)
    const float* Wh  = (const float*)d_in[11];
    const float* bh  = (const float*)d_in[12];
    const float* Lh  = (const float*)d_in[13];
    const float* lh  = (const float*)d_in[14];
    const float* Wo  = (const float*)d_in[15];
    const float* bo  = (const float*)d_in[16];
    float* out = (float*)d_out;

    int n = in_sizes[0] / 48;   // [N, 4, 12]
    int e = in_sizes[1] / 2;    // [2, E]
    int nchunks = n * 8;        // one uint4 per chunk, 8 per node (padded)

    k_fill <<<(e + 1023) / 1024, 256>>>(ei, e);
    k_cvt  <<<(nchunks + 255) / 256, 256>>>(x, nchunks,
                                            att, Wz, bz, Lz, lz, Wh, bh, Lh, lh, Wo, bo);
    k_fused<<<(n + 7) / 8, 256>>>(out, n);
}

// round 17
// speedup vs baseline: 1.0325x; 1.0325x over previous
#include <cuda_runtime.h>
#include <cuda_fp16.h>
#include <math.h>

// Problem constants (fixed dataset: N=50000, E=1.6M, avg in-degree 32)
#define MAXN 50048
#define CAP  128           // per-node adjacency capacity; Poisson(32) max << 128
#define ZROW (MAXN - 1)    // guaranteed all-zero row (never written; BSS zero-init)

struct Consts {
    float Mz[4][32];    // 0.5 * Wz @ Lz[0:32,:]   (0.5 from tanh(pz/2) folded in)
    float Mh[4][32];    // Wh @ Lh[0:32,:]
    float cz[32];       // 0.5 * (bz @ Lz[0:32,:] + lz)
    float ch[32];       // bh @ Lh[0:32,:] + lh
    float probs[12];    // 0.5 * softmax(attention)  (0.5 from GRU identity)
    float2 Wo2[16][32]; // Wo2[p][lane] = (Wo[2p][lane], Wo[2p+1][lane]); 0 for lane>=12
    float bo[12];
};
#define CONSTS_FLOATS (sizeof(Consts) / 4)

__device__ Consts g_c;
__device__ int   g_cnt[MAXN];               // zero-init at load; k_cvt re-zeroes
__device__ int   g_deg[MAXN];
__device__ float g_dinv[MAXN];
__device__ int   g_adj[(size_t)MAXN * CAP];
// One node row = 128 B = 8 x uint4: chunks 0-5 = 48 fp16 values of
// x[node]*dinv[node] in ORIGINAL order (flat idx f*12+t), chunks 6-7 zero.
// 128B-aligned rows: each gathered row = ONE L1 line. Rows >= n stay zero.
__device__ __align__(128) uint4 g_xh[(size_t)MAXN * 8];

// Packed f32x2 helpers (sm_103a packed-FMA pipe)
#define PACK2(out, lo, hi) \
    asm("mov.b64 %0, {%1, %2};" : "=l"(out) : "r"(__float_as_uint(lo)), "r"(__float_as_uint(hi)))
#define UNPACK2(lo, hi, in) \
    do { unsigned _a, _b; \
         asm("mov.b64 {%0, %1}, %2;" : "=r"(_a), "=r"(_b) : "l"(in)); \
         lo = __uint_as_float(_a); hi = __uint_as_float(_b); } while (0)
#define FMA2(d, a, b, c) \
    asm("fma.rn.f32x2 %0, %1, %2, %3;" : "=l"(d) : "l"(a), "l"(b), "l"(c))

// ---------------------------------------------------------------------------
// Kernel 1: bucketed adjacency build — best known config (R7): 256-thread
// blocks, 4 edges/thread.
// ---------------------------------------------------------------------------
__global__ void k_fill(const int* __restrict__ ei, int e) {
    int t = blockIdx.x * blockDim.x + threadIdx.x;
    int i4 = t * 4;
    if (i4 >= e) return;
    if ((e & 3) == 0) {   // dataset path: e divisible by 4
        int4 r = *reinterpret_cast<const int4*>(ei + i4);       // sources
        int4 c = *reinterpret_cast<const int4*>(ei + e + i4);   // targets
        int p0 = atomicAdd(&g_cnt[c.x], 1);
        int p1 = atomicAdd(&g_cnt[c.y], 1);
        int p2 = atomicAdd(&g_cnt[c.z], 1);
        int p3 = atomicAdd(&g_cnt[c.w], 1);
        if (p0 < CAP) g_adj[(size_t)c.x * CAP + p0] = r.x;
        if (p1 < CAP) g_adj[(size_t)c.y * CAP + p1] = r.y;
        if (p2 < CAP) g_adj[(size_t)c.z * CAP + p2] = r.z;
        if (p3 < CAP) g_adj[(size_t)c.w * CAP + p3] = r.w;
    } else {
        int end = min(i4 + 4, e);
        for (int i = i4; i < end; i++) {
            int rr = ei[i], cc = ei[e + i];
            int p = atomicAdd(&g_cnt[cc], 1);
            if (p < CAP) g_adj[(size_t)cc * CAP + p] = rr;
        }
    }
}

// ---------------------------------------------------------------------------
// Kernel 2 (after k_fill): per-node pack + integrated weight fold (block 0).
// dinv = rsqrt(cnt+1); pack fp16(x*dinv) row; write deg/dinv; re-zero cnt.
// ---------------------------------------------------------------------------
__global__ void k_cvt(const float* __restrict__ x, int nchunks,
                      const float* __restrict__ att,
                      const float* __restrict__ Wz, const float* __restrict__ bz,
                      const float* __restrict__ Lz, const float* __restrict__ lz,
                      const float* __restrict__ Wh, const float* __restrict__ bh,
                      const float* __restrict__ Lh, const float* __restrict__ lh,
                      const float* __restrict__ Wo, const float* __restrict__ bo) {
    if (blockIdx.x == 0 && threadIdx.x < 128) {
        int tid = threadIdx.x;
        int f = tid >> 5, c = tid & 31;
        float mz = 0.f, mh = 0.f;
        #pragma unroll 8
        for (int k = 0; k < 32; k++) {
            mz = fmaf(Wz[f * 32 + k], Lz[k * 32 + c], mz);
            mh = fmaf(Wh[f * 32 + k], Lh[k * 32 + c], mh);
        }
        g_c.Mz[f][c] = 0.5f * mz;   // tanh(pz/2): 0.5 folded into the matrix
        g_c.Mh[f][c] = mh;
        if (f == 0) {
            float s1 = lz[c], s2 = lh[c];
            #pragma unroll 8
            for (int k = 0; k < 32; k++) {
                s1 = fmaf(bz[k], Lz[k * 32 + c], s1);
                s2 = fmaf(bh[k], Lh[k * 32 + c], s2);
            }
            g_c.cz[c] = 0.5f * s1;
            g_c.ch[c] = s2;
        }
        // Wo2[p][lane] = (Wo[2p][lane], Wo[2p+1][lane]); lanes >= 12 -> 0
        for (int i = tid; i < 16 * 32; i += 128) {
            int p = i >> 5, cc = i & 31;
            float a = (cc < 12) ? Wo[(2 * p) * 12 + cc] : 0.f;
            float b = (cc < 12) ? Wo[(2 * p + 1) * 12 + cc] : 0.f;
            g_c.Wo2[p][cc] = make_float2(a, b);
        }
        if (tid < 12) g_c.bo[tid] = bo[tid];
        if (tid == 0) {
            float m = -1e30f;
            for (int t = 0; t < 12; t++) m = fmaxf(m, att[t]);
            float ex[12]; float s = 0.f;
            for (int t = 0; t < 12; t++) { ex[t] = expf(att[t] - m); s += ex[t]; }
            float inv = 0.5f / s;   // 0.5 from (1-sigmoid)*tanh identity
            for (int t = 0; t < 12; t++) g_c.probs[t] = ex[t] * inv;
        }
    }

    int i = blockIdx.x * blockDim.x + threadIdx.x;   // one uint4 out
    int node = i >> 3, h = i & 7;
    int d = 0;
    if (i < nchunks) d = g_cnt[node];
    __syncwarp();
    if (i >= nchunks) return;
    float dv = rsqrtf((float)d + 1.0f);   // +1 self loop
    uint4 o = make_uint4(0u, 0u, 0u, 0u);
    if (h < 6) {
        const float4* src = (const float4*)(x + (size_t)node * 48 + h * 8);
        float4 a = src[0];
        float4 b = src[1];
        __half2 h0 = __floats2half2_rn(a.x * dv, a.y * dv);
        __half2 h1 = __floats2half2_rn(a.z * dv, a.w * dv);
        __half2 h2 = __floats2half2_rn(b.x * dv, b.y * dv);
        __half2 h3 = __floats2half2_rn(b.z * dv, b.w * dv);
        o.x = *reinterpret_cast<unsigned*>(&h0);
        o.y = *reinterpret_cast<unsigned*>(&h1);
        o.z = *reinterpret_cast<unsigned*>(&h2);
        o.w = *reinterpret_cast<unsigned*>(&h3);
    } else if (h == 7) {
        g_cnt[node] = 0;                       // ready for next replay
        g_deg[node] = (d < CAP) ? d : CAP;
        g_dinv[node] = dv;
    }
    g_xh[i] = o;
}

// ---------------------------------------------------------------------------
// Kernel 3: fused warp-per-node gather + GRU (R15 structure).
// Mainloop: 16-edge full groups + a TAIL group whose 4-edge steps are
// predicated out when fully padded (kills ~8 pad edges/node of slot waste).
// Epilogue: f32x2 GRU (tanh(pz/2) fold) + f32x2 output projection.
// ---------------------------------------------------------------------------
__device__ __forceinline__ float fast_tanh(float v) {
    float r;
    asm("tanh.approx.f32 %0, %1;" : "=f"(r) : "f"(v));
    return r;
}

__device__ __forceinline__ void hadd4(__half2* hacc, const uint4& c) {
    hacc[0] = __hadd2(hacc[0], *reinterpret_cast<const __half2*>(&c.x));
    hacc[1] = __hadd2(hacc[1], *reinterpret_cast<const __half2*>(&c.y));
    hacc[2] = __hadd2(hacc[2], *reinterpret_cast<const __half2*>(&c.z));
    hacc[3] = __hadd2(hacc[3], *reinterpret_cast<const __half2*>(&c.w));
}

__device__ __forceinline__ void flush8(float* acc, __half2* hacc) {
    #pragma unroll
    for (int j = 0; j < 4; j++) {
        float2 f = __half22float2(hacc[j]);
        acc[2 * j]     += f.x;
        acc[2 * j + 1] += f.y;
        hacc[j] = __half2(__ushort_as_half(0), __ushort_as_half(0));
    }
}

__global__ void __launch_bounds__(256, 6) k_fused(float* __restrict__ out, int n) {
    __shared__ __align__(16) float sC[CONSTS_FLOATS];
    __shared__ __align__(16) float sXA[8][48];     // per-warp XA (f-major) / H
    {
        const float* src = (const float*)&g_c;
        for (int i = threadIdx.x; i < (int)CONSTS_FLOATS; i += 256) sC[i] = src[i];
    }
    __syncthreads();
    const Consts* C = (const Consts*)sC;

    const unsigned FULL = 0xffffffffu;
    int warp = threadIdx.x >> 5, lane = threadIdx.x & 31;
    int node = blockIdx.x * 8 + warp;
    if (node >= n) return;

    int myslot = lane >> 3;   // 0..3: which of the 4 concurrent edges
    int h = lane & 7;         // 16B chunk within the row
    int deg = g_deg[node];
    float dn = g_dinv[node];
    const int* adj = g_adj + (size_t)node * CAP;

    float acc[8];
    #pragma unroll
    for (int k = 0; k < 8; k++) acc[k] = 0.f;
    __half2 hacc[4];
    #pragma unroll
    for (int j = 0; j < 4; j++) hacc[j] = __half2(__ushort_as_half(0), __ushort_as_half(0));

    // self loop: own pre-scaled row; final *dn makes it dn^2 * x.
    if (myslot == 0) hadd4(hacc, g_xh[(size_t)node * 8 + h]);

    int fullIters = deg >> 4;     // full 16-edge groups
    int rem = deg & 15;           // tail edges (0..15)
    // prefetch group 0's indices (lanes 0-15); pads -> zero row
    int s = ZROW;
    if (lane < 16 && lane < deg) s = adj[lane];

    for (int it = 0; it < fullIters; it++) {
        int cur_s = s;
        int base = (it + 1) * 16;
        if (lane < 16) {
            int idx = base + lane;
            s = (idx < deg) ? adj[idx] : ZROW;
        }
        #pragma unroll
        for (int k = 0; k < 4; k++) {
            int row = __shfl_sync(FULL, cur_s, 4 * k + myslot);
            hadd4(hacc, g_xh[(size_t)row * 8 + h]);
        }
        flush8(acc, hacc);   // fp16 depth per group stays <= 5
    }
    // tail group: skip fully-padded 4-edge steps entirely.
    {
        int cur_s = s;
        #pragma unroll
        for (int k = 0; k < 4; k++) {
            if (4 * k < rem) {
                int row = __shfl_sync(FULL, cur_s, 4 * k + myslot);
                hadd4(hacc, g_xh[(size_t)row * 8 + h]);
            }
        }
        flush8(acc, hacc);   // also flushes the self loop when deg < 16
    }

    // butterfly over the 4 slots (lanes with equal h), then norm.
    #pragma unroll
    for (int d = 8; d < 32; d <<= 1) {
        #pragma unroll
        for (int k = 0; k < 8; k++)
            acc[k] += __shfl_xor_sync(FULL, acc[k], d);
    }
    #pragma unroll
    for (int k = 0; k < 8; k++) acc[k] *= dn;

    // XA to smem in ORIGINAL f-major order (flat idx f*12+t): lane h owns
    // elements 8h..8h+7 -> two contiguous STS.128, no transpose needed.
    float* xaf = sXA[warp];
    if (lane < 6) {
        float4* dst = (float4*)(xaf + lane * 8);
        dst[0] = make_float4(acc[0], acc[1], acc[2], acc[3]);
        dst[1] = make_float4(acc[4], acc[5], acc[6], acc[7]);
    }
    __syncwarp();

    // collapsed GRU: lane = output channel c; t in PAIRS with packed f32x2.
    unsigned long long Mz0p, Mz1p, Mz2p, Mz3p, Mh0p, Mh1p, Mh2p, Mh3p, czp, chp;
    PACK2(Mz0p, C->Mz[0][lane], C->Mz[0][lane]);
    PACK2(Mz1p, C->Mz[1][lane], C->Mz[1][lane]);
    PACK2(Mz2p, C->Mz[2][lane], C->Mz[2][lane]);
    PACK2(Mz3p, C->Mz[3][lane], C->Mz[3][lane]);
    PACK2(Mh0p, C->Mh[0][lane], C->Mh[0][lane]);
    PACK2(Mh1p, C->Mh[1][lane], C->Mh[1][lane]);
    PACK2(Mh2p, C->Mh[2][lane], C->Mh[2][lane]);
    PACK2(Mh3p, C->Mh[3][lane], C->Mh[3][lane]);
    PACK2(czp, C->cz[lane], C->cz[lane]);
    PACK2(chp, C->ch[lane], C->ch[lane]);

    float H = 0.f;
    #pragma unroll
    for (int tp = 0; tp < 6; tp++) {
        unsigned long long xv0 = *(const unsigned long long*)(xaf +      2 * tp);
        unsigned long long xv1 = *(const unsigned long long*)(xaf + 12 + 2 * tp);
        unsigned long long xv2 = *(const unsigned long long*)(xaf + 24 + 2 * tp);
        unsigned long long xv3 = *(const unsigned long long*)(xaf + 36 + 2 * tp);
        unsigned long long pzp, php;
        FMA2(pzp, xv3, Mz3p, czp);
        FMA2(pzp, xv2, Mz2p, pzp);
        FMA2(pzp, xv1, Mz1p, pzp);
        FMA2(pzp, xv0, Mz0p, pzp);
        FMA2(php, xv3, Mh3p, chp);
        FMA2(php, xv2, Mh2p, php);
        FMA2(php, xv1, Mh1p, php);
        FMA2(php, xv0, Mh0p, php);
        float pz0, pz1, ph0, ph1;
        UNPACK2(pz0, pz1, pzp);
        UNPACK2(ph0, ph1, php);
        // (1 - sigmoid(pz)) * tanh(ph) = 0.5*(1 - tanh(pz/2))*tanh(ph);
        // pz/2 folded into Mz/cz, 0.5 into probs.
        float tA0 = fast_tanh(pz0), tB0 = fast_tanh(ph0);
        float tA1 = fast_tanh(pz1), tB1 = fast_tanh(ph1);
        H = fmaf((1.0f - tA0) * tB0, C->probs[2 * tp],     H);
        H = fmaf((1.0f - tA1) * tB1, C->probs[2 * tp + 1], H);
    }

    // Output projection (packed f32x2): reuse smem buffer for relu(H).
    __syncwarp();
    xaf[lane] = fmaxf(H, 0.f);
    __syncwarp();
    if (lane < 12) {
        unsigned long long accp;
        PACK2(accp, C->bo[lane], 0.f);
        #pragma unroll
        for (int p = 0; p < 16; p++) {
            unsigned long long hp = *(const unsigned long long*)(xaf + 2 * p);  // uniform
            unsigned long long wp = *(const unsigned long long*)(&C->Wo2[p][lane]);
            FMA2(accp, hp, wp, accp);
        }
        float lo, hi;
        UNPACK2(lo, hi, accp);
        out[(size_t)node * 12 + lane] = lo + hi;
    }
}

// ---------------------------------------------------------------------------
extern "C" void kernel_launch(void* const* d_in, const int* in_sizes, int n_in,
                              void* d_out, int out_size) {
    const float* x   = (const float*)d_in[0];
    const int*   ei  = (const int*)  d_in[1];
    const float* att = (const float*)d_in[2];
    const float* Wz  = (const float*)d_in[3];
    const float* bz  = (const float*)d_in[4];
    const float* Lz  = (const float*)d_in[5];
    const float* lz  = (const float*)d_in[6];
    // d_in[7..10] = Wr, br, Lr, lr : provably unused (H0 == 0)
    const float* Wh  = (const float*)d_in[11];
    const float* bh  = (const float*)d_in[12];
    const float* Lh  = (const float*)d_in[13];
    const float* lh  = (const float*)d_in[14];
    const float* Wo  = (const float*)d_in[15];
    const float* bo  = (const float*)d_in[16];
    float* out = (float*)d_out;

    int n = in_sizes[0] / 48;   // [N, 4, 12]
    int e = in_sizes[1] / 2;    // [2, E]
    int nchunks = n * 8;        // one uint4 per chunk, 8 per node (padded)

    k_fill <<<(e + 1023) / 1024, 256>>>(ei, e);
    k_cvt  <<<(nchunks + 255) / 256, 256>>>(x, nchunks,
                                            att, Wz, bz, Lz, lz, Wh, bh, Lh, lh, Wo, bo);
    k_fused<<<(n + 7) / 8, 256>>>(out, n);
}